// round 12
// baseline (speedup 1.0000x reference)
#include <cuda_runtime.h>

#define TT 2048
#define MM 64
#define HH 256
#define DINN 256
#define DOUTT 256
#define MH (MM*HH)
#define NBLK 64
#define WX_SROWS 192          // Wx k-rows cached in SMEM
#define WH_SROWS 28           // Wh k-rows cached in SMEM (220KB total)
#define CHUNK 128             // steps per launch -> 16 launches

// ---------------- device scratch ----------------
__device__ float    g_X[TT * HH];
__device__ float    g_Hh[(TT + 1) * MH];
__device__ int      g_act[MM * MM];
__device__ int      g_nact[MM];
__device__ int      g_inm[MM];
__device__ unsigned g_cnt;

// ---------------- XLA:GPU EmitTanh ----------------------------------------
// outer: |x| >= 20 -> copysign(1, x)
// inner EmitFastTanh(with_fma=true): clamp +-7.99881172180175781,
//   |x| < 0.0004 -> x, rational P13/Q6 with fmuladd (FMA) contraction, IEEE div.
__device__ __forceinline__ float tanh_ref(float x) {
    const float kClamp = 7.99881172180175781f;
    float xc = fminf(fmaxf(x, -kClamp), kClamp);
    float x2 = __fmul_rn(xc, xc);
    float p = -2.76076847742355e-16f;
    p = fmaf(p, x2,  2.00018790482477e-13f);
    p = fmaf(p, x2, -8.60467152213735e-11f);
    p = fmaf(p, x2,  5.12229709037114e-08f);
    p = fmaf(p, x2,  1.48572235717979e-05f);
    p = fmaf(p, x2,  6.37261928875436e-04f);
    p = fmaf(p, x2,  4.89352455891786e-03f);
    p = __fmul_rn(xc, p);
    float q = 1.19825839466702e-06f;
    q = fmaf(q, x2,  1.18534705686654e-04f);
    q = fmaf(q, x2,  2.26843463243900e-03f);
    q = fmaf(q, x2,  4.89352518554385e-03f);
    float r = __fdiv_rn(p, q);
    r = (fabsf(x) < 0.0004f) ? x : r;
    return (fabsf(x) < 20.0f) ? r : copysignf(1.0f, x);
}

// ---------------- init (every replay) ------------------------------------
__global__ void k_init() {
    int i = blockIdx.x * blockDim.x + threadIdx.x;
    if (i < MH) g_Hh[i] = 0.0f;
    if (i == 0) g_cnt = 0u;
}

__global__ void k_setup(const int* __restrict__ conn, const int* __restrict__ in_conn) {
    int m = threadIdx.x;
    int n = 0;
    for (int i = 0; i < MM; i++)
        if (conn[i * MM + m]) g_act[m * MM + (n++)] = i;   // ascending i
    g_nact[m] = n;
    g_inm[m]  = in_conn[m];
}

// ---------------- X = x_seq @ in_proj (ascending-k fmaf chain) -----------
__global__ void k_inproj(const float* __restrict__ x, const float* __restrict__ P) {
    __shared__ float xs[8][DINN];
    int t0 = blockIdx.x * 8;
    int c  = threadIdx.x;
    #pragma unroll
    for (int j = 0; j < 8; j++) xs[j][c] = x[(size_t)(t0 + j) * DINN + c];
    __syncthreads();
    float acc[8] = {0, 0, 0, 0, 0, 0, 0, 0};
    for (int k = 0; k < DINN; k++) {
        float p = __ldg(&P[(size_t)k * HH + c]);
        #pragma unroll
        for (int j = 0; j < 8; j++) acc[j] = fmaf(xs[j][k], p, acc[j]);
    }
    #pragma unroll
    for (int j = 0; j < 8; j++) g_X[(size_t)(t0 + j) * HH + c] = acc[j];
}

// ---------------- CHUNK fused RNN steps ----------------------------------
// 64 CTAs (1 module each, co-resident), 128 threads:
//   threads  0..63  : Wx chains for 4 output cols each (ascending k, fmaf)
//   threads 64..127 : Wh chains for 4 output cols each, then combine+tanh+store
__global__ void __launch_bounds__(128, 1)
k_chunk(const float* __restrict__ Wx, const float* __restrict__ Wh,
        const float* __restrict__ b, int t0)
{
    extern __shared__ float s_w[];     // [WX_SROWS*HH] Wx rows, then [WH_SROWS*HH] Wh rows
    __shared__ __align__(16) float inp_s[HH];
    __shared__ __align__(16) float hp_s[HH];
    __shared__ __align__(16) float red_s[HH];
    __shared__ int act[MM];

    const int m   = blockIdx.x;
    const int tid = threadIdx.x;
    const float* WxM = Wx + (size_t)m * HH * HH;
    const float* WhM = Wh + (size_t)m * HH * HH;

    // stage weight caches
    {
        const float4* s1 = (const float4*)WxM;
        float4* d1 = (float4*)s_w;
        for (int i = tid; i < WX_SROWS * HH / 4; i += 128) d1[i] = s1[i];
        const float4* s2 = (const float4*)WhM;
        float4* d2 = (float4*)(s_w + WX_SROWS * HH);
        for (int i = tid; i < WH_SROWS * HH / 4; i += 128) d2[i] = s2[i];
    }
    if (tid < MM) act[tid] = g_act[m * MM + tid];
    const int n_act = g_nact[m];
    const int inm   = g_inm[m];
    const int wsel  = tid >> 6;          // 0: Wx, 1: Wh
    const int o4    = (tid & 63) * 4;
    float4 bias4 = make_float4(0.f, 0.f, 0.f, 0.f);
    if (wsel) bias4 = *(const float4*)(b + (size_t)m * HH + o4);
    __syncthreads();

    for (int s = 0; s < CHUNK; s++) {
        const int t = t0 + s;
        const float* hc = g_Hh + (size_t)t * MH;

        // ---- phase A: inp = rec + ext (rec ascending i; exact w/ 0-1 mask) ----
        {
            const int k0 = tid, k1 = tid + 128;
            float r0 = 0.f, r1 = 0.f;
            #pragma unroll 4
            for (int a = 0; a < n_act; a++) {
                const float* hp = hc + act[a] * HH;
                r0 += __ldcg(hp + k0);
                r1 += __ldcg(hp + k1);
            }
            float e0 = inm ? g_X[(size_t)t * HH + k0] : 0.0f;
            float e1 = inm ? g_X[(size_t)t * HH + k1] : 0.0f;
            inp_s[k0] = __fadd_rn(r0, e0);
            inp_s[k1] = __fadd_rn(r1, e1);
            hp_s[k0]  = __ldcg(hc + m * HH + k0);
            hp_s[k1]  = __ldcg(hc + m * HH + k1);
        }
        __syncthreads();

        // ---- phase B: ascending-k single-accumulator fmaf chains ----
        float4 acc = make_float4(0.f, 0.f, 0.f, 0.f);
        if (wsel == 0) {
            #pragma unroll 4
            for (int k = 0; k < WX_SROWS; k++) {
                float sv = inp_s[k];
                float4 w = *(const float4*)(s_w + (size_t)k * HH + o4);
                acc.x = fmaf(sv, w.x, acc.x); acc.y = fmaf(sv, w.y, acc.y);
                acc.z = fmaf(sv, w.z, acc.z); acc.w = fmaf(sv, w.w, acc.w);
            }
            #pragma unroll 4
            for (int k = WX_SROWS; k < HH; k++) {
                float sv = inp_s[k];
                float4 w = __ldcg((const float4*)(WxM + (size_t)k * HH + o4));
                acc.x = fmaf(sv, w.x, acc.x); acc.y = fmaf(sv, w.y, acc.y);
                acc.z = fmaf(sv, w.z, acc.z); acc.w = fmaf(sv, w.w, acc.w);
            }
            *(float4*)(red_s + o4) = acc;
        } else {
            #pragma unroll 4
            for (int k = 0; k < WH_SROWS; k++) {
                float sv = hp_s[k];
                float4 w = *(const float4*)(s_w + WX_SROWS * HH + (size_t)k * HH + o4);
                acc.x = fmaf(sv, w.x, acc.x); acc.y = fmaf(sv, w.y, acc.y);
                acc.z = fmaf(sv, w.z, acc.z); acc.w = fmaf(sv, w.w, acc.w);
            }
            #pragma unroll 4
            for (int k = WH_SROWS; k < HH; k++) {
                float sv = hp_s[k];
                float4 w = __ldcg((const float4*)(WhM + (size_t)k * HH + o4));
                acc.x = fmaf(sv, w.x, acc.x); acc.y = fmaf(sv, w.y, acc.y);
                acc.z = fmaf(sv, w.z, acc.z); acc.w = fmaf(sv, w.w, acc.w);
            }
        }
        __syncthreads();

        // ---- combine (e1 + e2) + b, reference tanh, store ----
        if (wsel) {
            float4 aX = *(const float4*)(red_s + o4);
            float r0 = __fadd_rn(__fadd_rn(aX.x, acc.x), bias4.x);
            float r1 = __fadd_rn(__fadd_rn(aX.y, acc.y), bias4.y);
            float r2 = __fadd_rn(__fadd_rn(aX.z, acc.z), bias4.z);
            float r3 = __fadd_rn(__fadd_rn(aX.w, acc.w), bias4.w);
            float* hd = g_Hh + (size_t)(t + 1) * MH + (size_t)m * HH + o4;
            __stcg(hd + 0, tanh_ref(r0));
            __stcg(hd + 1, tanh_ref(r1));
            __stcg(hd + 2, tanh_ref(r2));
            __stcg(hd + 3, tanh_ref(r3));
        }
        __threadfence();
        __syncthreads();

        // ---- monotonic grid barrier ----
        if (tid == 0) {
            atomicAdd(&g_cnt, 1u);
            if (s < CHUNK - 1) {
                const unsigned target = (unsigned)(t + 1) * NBLK;
                volatile unsigned* c = &g_cnt;
                while (*c < target) __nanosleep(32);
                __threadfence();
            }
        }
        __syncthreads();
    }
}

// ---------------- outputs[t] (not fed back; ~1e-6 any order) -------------
__global__ void k_outproj(const float* __restrict__ P, const int* __restrict__ out_conn,
                          float* __restrict__ out)
{
    __shared__ float Ss[8][HH];
    __shared__ int oact[MM];
    __shared__ int n_o_s;
    int t0 = blockIdx.x * 8;
    int c  = threadIdx.x;
    if (c == 0) {
        int n = 0;
        for (int i = 0; i < MM; i++) if (out_conn[i]) oact[n++] = i;
        n_o_s = n;
    }
    __syncthreads();
    const int n_o = n_o_s;
    for (int j = 0; j < 8; j++) {
        const float* hr = g_Hh + (size_t)(t0 + j + 1) * MH;
        float s = 0.0f;
        for (int a = 0; a < n_o; a++) s += hr[oact[a] * HH + c];
        Ss[j][c] = s;
    }
    __syncthreads();
    float acc[8] = {0, 0, 0, 0, 0, 0, 0, 0};
    for (int k = 0; k < HH; k++) {
        float p = __ldg(&P[(size_t)k * DOUTT + c]);
        #pragma unroll
        for (int j = 0; j < 8; j++) acc[j] = fmaf(Ss[j][k], p, acc[j]);
    }
    #pragma unroll
    for (int j = 0; j < 8; j++) out[(size_t)(t0 + j) * DOUTT + c] = acc[j];
}

__global__ void k_hfinal(float* __restrict__ out) {
    int i = blockIdx.x * blockDim.x + threadIdx.x;
    out[(size_t)TT * DOUTT + i] = g_Hh[(size_t)TT * MH + i];
}

// ---------------- launch ---------------------------------------------------
extern "C" void kernel_launch(void* const* d_in, const int* in_sizes, int n_in,
                              void* d_out, int out_size) {
    const float *x = 0, *Wx = 0, *Wh = 0, *b = 0, *inP = 0, *outP = 0;
    const int *conn = 0, *in_conn = 0, *out_conn = 0;

    bool alpha = (n_in >= 2 && in_sizes[0] == MM * HH * HH && in_sizes[1] == MM * HH * HH);
    int nW = 0, nP = 0, nC = 0;
    for (int i = 0; i < n_in; i++) {
        int s = in_sizes[i];
        if (s == TT * DINN)           x = (const float*)d_in[i];
        else if (s == MM * HH * HH) {
            if (nW == 0) { if (alpha) Wh = (const float*)d_in[i]; else Wx = (const float*)d_in[i]; }
            else         { if (alpha) Wx = (const float*)d_in[i]; else Wh = (const float*)d_in[i]; }
            nW++;
        }
        else if (s == MM * HH)        b = (const float*)d_in[i];
        else if (s == DINN * HH) {
            if (nP == 0) inP = (const float*)d_in[i]; else outP = (const float*)d_in[i];
            nP++;
        }
        else if (s == MM * MM)        conn = (const int*)d_in[i];
        else if (s == MM) {
            if (nC == 0) in_conn = (const int*)d_in[i]; else out_conn = (const int*)d_in[i];
            nC++;
        }
    }
    float* out = (float*)d_out;

    cudaFuncSetAttribute((const void*)k_chunk,
                         cudaFuncAttributeMaxDynamicSharedMemorySize,
                         (WX_SROWS + WH_SROWS) * HH * (int)sizeof(float));

    k_init  <<<64, 256>>>();
    k_setup <<<1, 64>>>(conn, in_conn);
    k_inproj<<<TT / 8, 256>>>(x, inP);
    for (int t0 = 0; t0 < TT; t0 += CHUNK)
        k_chunk<<<NBLK, 128, (WX_SROWS + WH_SROWS) * HH * sizeof(float)>>>(Wx, Wh, b, t0);
    k_outproj<<<TT / 8, 256>>>(outP, out_conn, out);
    if (out_size >= TT * DOUTT + MM * HH)
        k_hfinal<<<MH / 256, 256>>>(out);
}

// round 13
// speedup vs baseline: 2.6780x; 2.6780x over previous
#include <cuda_runtime.h>

#define TT 2048
#define MM 64
#define HH 256
#define DINN 256
#define DOUTT 256
#define MH (MM*HH)
#define NCTA 128           // 2 CTAs per module
#define SROWS 200          // weight k-rows in SMEM per matrix (x2 = 204.8KB)
#define RROWS 56           // weight k-rows in registers per matrix (56 float2 = 112 regs)
#define CHUNK 128          // steps per launch -> 16 launches

// ---------------- device scratch ----------------
__device__ float    g_X[TT * HH];
__device__ float    g_Hh[(TT + 1) * MH];
__device__ int      g_act[MM * MM];
__device__ int      g_nact[MM];
__device__ int      g_inm[MM];
__device__ unsigned g_cnt;

// ---------------- XLA:GPU EmitTanh (verified bit-exact in R12) -------------
__device__ __forceinline__ float tanh_ref(float x) {
    const float kClamp = 7.99881172180175781f;
    float xc = fminf(fmaxf(x, -kClamp), kClamp);
    float x2 = __fmul_rn(xc, xc);
    float p = -2.76076847742355e-16f;
    p = fmaf(p, x2,  2.00018790482477e-13f);
    p = fmaf(p, x2, -8.60467152213735e-11f);
    p = fmaf(p, x2,  5.12229709037114e-08f);
    p = fmaf(p, x2,  1.48572235717979e-05f);
    p = fmaf(p, x2,  6.37261928875436e-04f);
    p = fmaf(p, x2,  4.89352455891786e-03f);
    p = __fmul_rn(xc, p);
    float q = 1.19825839466702e-06f;
    q = fmaf(q, x2,  1.18534705686654e-04f);
    q = fmaf(q, x2,  2.26843463243900e-03f);
    q = fmaf(q, x2,  4.89352518554385e-03f);
    float r = __fdiv_rn(p, q);
    r = (fabsf(x) < 0.0004f) ? x : r;
    return (fabsf(x) < 20.0f) ? r : copysignf(1.0f, x);
}

// ---------------- init (every replay) ------------------------------------
__global__ void k_init() {
    int i = blockIdx.x * blockDim.x + threadIdx.x;
    if (i < MH) g_Hh[i] = 0.0f;
    if (i == 0) g_cnt = 0u;
}

__global__ void k_setup(const int* __restrict__ conn, const int* __restrict__ in_conn) {
    int m = threadIdx.x;
    int n = 0;
    for (int i = 0; i < MM; i++)
        if (conn[i * MM + m]) g_act[m * MM + (n++)] = i;   // ascending i
    g_nact[m] = n;
    g_inm[m]  = in_conn[m];
}

// ---------------- X = x_seq @ in_proj (bit-exact path; unchanged) --------
__global__ void k_inproj(const float* __restrict__ x, const float* __restrict__ P) {
    __shared__ float xs[8][DINN];
    int t0 = blockIdx.x * 8;
    int c  = threadIdx.x;
    #pragma unroll
    for (int j = 0; j < 8; j++) xs[j][c] = x[(size_t)(t0 + j) * DINN + c];
    __syncthreads();
    float acc[8] = {0, 0, 0, 0, 0, 0, 0, 0};
    for (int k = 0; k < DINN; k++) {
        float p = __ldg(&P[(size_t)k * HH + c]);
        #pragma unroll
        for (int j = 0; j < 8; j++) acc[j] = fmaf(xs[j][k], p, acc[j]);
    }
    #pragma unroll
    for (int j = 0; j < 8; j++) g_X[(size_t)(t0 + j) * HH + c] = acc[j];
}

// ---------------- CHUNK fused RNN steps ----------------------------------
// 128 CTAs: module m = bid>>1, output-column half = bid&1 (cols obase..obase+127).
// 128 threads: tid 0..63 = Wx chains, tid 64..127 = Wh chains; 2 cols/thread.
// All weights SMEM- or register-resident -> zero per-step L2 weight traffic.
__global__ void __launch_bounds__(128, 1)
k_chunk(const float* __restrict__ Wx, const float* __restrict__ Wh,
        const float* __restrict__ b, int t0)
{
    extern __shared__ float s_w[];     // [2][SROWS][128] slice-local weights
    __shared__ __align__(16) float inp_s[HH];
    __shared__ __align__(16) float hp_s[HH];
    __shared__ __align__(16) float red_s[128];
    __shared__ int act[MM];

    const int bid   = blockIdx.x;
    const int m     = bid >> 1;
    const int obase = (bid & 1) * 128;
    const int tid   = threadIdx.x;
    const int wsel  = tid >> 6;              // 0: Wx, 1: Wh
    const int cc    = (tid & 63) * 2;        // slice-local col pair
    const float* WxM = Wx + (size_t)m * HH * HH;
    const float* WhM = Wh + (size_t)m * HH * HH;

    // ---- stage SMEM weight slices (rows [0,SROWS) of both matrices) ----
    for (int i = tid; i < SROWS * 32; i += 128) {       // float4 units
        int k  = i >> 5;
        int c4 = (i & 31) << 2;
        *(float4*)(s_w + (size_t)k * 128 + c4) =
            *(const float4*)(WxM + (size_t)k * HH + obase + c4);
        *(float4*)(s_w + (size_t)SROWS * 128 + (size_t)k * 128 + c4) =
            *(const float4*)(WhM + (size_t)k * HH + obase + c4);
    }
    // ---- stage register weight rows [SROWS,256) for this thread's matrix ----
    float2 wr[RROWS];
    {
        const float* Wm = wsel ? WhM : WxM;
        #pragma unroll
        for (int j = 0; j < RROWS; j++)
            wr[j] = *(const float2*)(Wm + (size_t)(SROWS + j) * HH + obase + cc);
    }
    if (tid < MM) act[tid] = g_act[m * MM + tid];
    const int n_act = g_nact[m];
    const int inm   = g_inm[m];
    float b0 = 0.f, b1 = 0.f;
    if (wsel) { b0 = b[(size_t)m * HH + obase + cc];
                b1 = b[(size_t)m * HH + obase + cc + 1]; }
    const float* vsrc = wsel ? hp_s : inp_s;
    const float* wsm  = s_w + (wsel ? (size_t)SROWS * 128 : 0);
    __syncthreads();

    for (int s = 0; s < CHUNK; s++) {
        const int t = t0 + s;
        const float* hc = g_Hh + (size_t)t * MH;

        // ---- phase A: inp = rec + ext (per-element order identical to R12) ----
        {
            const int k2 = 2 * tid;
            float r0 = 0.f, r1 = 0.f;
            #pragma unroll 8
            for (int a = 0; a < n_act; a++) {
                float2 hv = __ldcg((const float2*)(hc + act[a] * HH + k2));
                r0 += hv.x;
                r1 += hv.y;
            }
            float e0 = inm ? g_X[(size_t)t * HH + k2]     : 0.0f;
            float e1 = inm ? g_X[(size_t)t * HH + k2 + 1] : 0.0f;
            inp_s[k2]     = __fadd_rn(r0, e0);
            inp_s[k2 + 1] = __fadd_rn(r1, e1);
            float2 hp = __ldcg((const float2*)(hc + (size_t)m * HH + k2));
            hp_s[k2]     = hp.x;
            hp_s[k2 + 1] = hp.y;
        }
        __syncthreads();

        // ---- phase B: ascending-k single-accumulator fmaf chains (2 cols) ----
        float a0 = 0.f, a1 = 0.f;
        #pragma unroll 8
        for (int k = 0; k < SROWS; k++) {
            float sv = vsrc[k];
            float2 w = *(const float2*)(wsm + (size_t)k * 128 + cc);
            a0 = fmaf(sv, w.x, a0);
            a1 = fmaf(sv, w.y, a1);
        }
        #pragma unroll
        for (int j = 0; j < RROWS; j++) {
            float sv = vsrc[SROWS + j];
            a0 = fmaf(sv, wr[j].x, a0);
            a1 = fmaf(sv, wr[j].y, a1);
        }
        if (!wsel) { red_s[cc] = a0; red_s[cc + 1] = a1; }
        __syncthreads();

        // ---- combine (e1 + e2) + b, tanh, store (Wh threads) ----
        if (wsel) {
            float r0 = __fadd_rn(__fadd_rn(red_s[cc],     a0), b0);
            float r1 = __fadd_rn(__fadd_rn(red_s[cc + 1], a1), b1);
            float2 hv = make_float2(tanh_ref(r0), tanh_ref(r1));
            __stcg((float2*)(g_Hh + (size_t)(t + 1) * MH + (size_t)m * HH + obase + cc), hv);
        }
        __threadfence();
        __syncthreads();

        // ---- monotonic grid barrier (128 arrivals per step) ----
        if (tid == 0) {
            atomicAdd(&g_cnt, 1u);
            if (s < CHUNK - 1) {
                const unsigned target = (unsigned)(t + 1) * NCTA;
                volatile unsigned* c = &g_cnt;
                while (*c < target) __nanosleep(32);
                __threadfence();
            }
        }
        __syncthreads();
    }
}

// ---------------- outputs[t] (not fed back; unchanged) -------------------
__global__ void k_outproj(const float* __restrict__ P, const int* __restrict__ out_conn,
                          float* __restrict__ out)
{
    __shared__ float Ss[8][HH];
    __shared__ int oact[MM];
    __shared__ int n_o_s;
    int t0 = blockIdx.x * 8;
    int c  = threadIdx.x;
    if (c == 0) {
        int n = 0;
        for (int i = 0; i < MM; i++) if (out_conn[i]) oact[n++] = i;
        n_o_s = n;
    }
    __syncthreads();
    const int n_o = n_o_s;
    for (int j = 0; j < 8; j++) {
        const float* hr = g_Hh + (size_t)(t0 + j + 1) * MH;
        float s = 0.0f;
        for (int a = 0; a < n_o; a++) s += hr[oact[a] * HH + c];
        Ss[j][c] = s;
    }
    __syncthreads();
    float acc[8] = {0, 0, 0, 0, 0, 0, 0, 0};
    for (int k = 0; k < HH; k++) {
        float p = __ldg(&P[(size_t)k * DOUTT + c]);
        #pragma unroll
        for (int j = 0; j < 8; j++) acc[j] = fmaf(Ss[j][k], p, acc[j]);
    }
    #pragma unroll
    for (int j = 0; j < 8; j++) out[(size_t)(t0 + j) * DOUTT + c] = acc[j];
}

__global__ void k_hfinal(float* __restrict__ out) {
    int i = blockIdx.x * blockDim.x + threadIdx.x;
    out[(size_t)TT * DOUTT + i] = g_Hh[(size_t)TT * MH + i];
}

// ---------------- launch ---------------------------------------------------
extern "C" void kernel_launch(void* const* d_in, const int* in_sizes, int n_in,
                              void* d_out, int out_size) {
    const float *x = 0, *Wx = 0, *Wh = 0, *b = 0, *inP = 0, *outP = 0;
    const int *conn = 0, *in_conn = 0, *out_conn = 0;

    bool alpha = (n_in >= 2 && in_sizes[0] == MM * HH * HH && in_sizes[1] == MM * HH * HH);
    int nW = 0, nP = 0, nC = 0;
    for (int i = 0; i < n_in; i++) {
        int s = in_sizes[i];
        if (s == TT * DINN)           x = (const float*)d_in[i];
        else if (s == MM * HH * HH) {
            if (nW == 0) { if (alpha) Wh = (const float*)d_in[i]; else Wx = (const float*)d_in[i]; }
            else         { if (alpha) Wx = (const float*)d_in[i]; else Wh = (const float*)d_in[i]; }
            nW++;
        }
        else if (s == MM * HH)        b = (const float*)d_in[i];
        else if (s == DINN * HH) {
            if (nP == 0) inP = (const float*)d_in[i]; else outP = (const float*)d_in[i];
            nP++;
        }
        else if (s == MM * MM)        conn = (const int*)d_in[i];
        else if (s == MM) {
            if (nC == 0) in_conn = (const int*)d_in[i]; else out_conn = (const int*)d_in[i];
            nC++;
        }
    }
    float* out = (float*)d_out;

    const int dyn = 2 * SROWS * 128 * (int)sizeof(float);   // 204,800 B
    cudaFuncSetAttribute((const void*)k_chunk,
                         cudaFuncAttributeMaxDynamicSharedMemorySize, dyn);

    k_init  <<<64, 256>>>();
    k_setup <<<1, 64>>>(conn, in_conn);
    k_inproj<<<TT / 8, 256>>>(x, inP);
    for (int t0 = 0; t0 < TT; t0 += CHUNK)
        k_chunk<<<NCTA, 128, dyn>>>(Wx, Wh, b, t0);
    k_outproj<<<TT / 8, 256>>>(outP, out_conn, out);
    if (out_size >= TT * DOUTT + MM * HH)
        k_hfinal<<<MH / 256, 256>>>(out);
}